// round 1
// baseline (speedup 1.0000x reference)
#include <cuda_runtime.h>

// x: [16, 64, 256, 256] f32  ->  out: [16, 64, 128, 128] f32
// Per 2x2 window: m = max|v_i|; out = max_i(|v_i|==m ? v_i : 0).
// NC = 16*64 = 1024, H=W=256, OH=OW=128.
// One thread -> 2 output pixels (4-wide input span): 2x LDG.128 + 1x STG.64.

static __device__ __forceinline__ float win_result(float a, float b, float c, float d) {
    float aa = fabsf(a), ab = fabsf(b), ac = fabsf(c), ad = fabsf(d);
    float m = fmaxf(fmaxf(aa, ab), fmaxf(ac, ad));
    float r = fmaxf(fmaxf(aa == m ? a : 0.0f, ab == m ? b : 0.0f),
                    fmaxf(ac == m ? c : 0.0f, ad == m ? d : 0.0f));
    return r;
}

__global__ __launch_bounds__(256) void maxabspool_kernel(
    const float* __restrict__ x, float* __restrict__ out)
{
    // total threads = NC * OH * (OW/2) = 1024 * 128 * 64 = 8388608
    unsigned idx = blockIdx.x * 256u + threadIdx.x;

    unsigned owp = idx & 63u;            // output pixel pair index, 0..63
    unsigned oh  = (idx >> 6) & 127u;    // 0..127
    unsigned nc  = idx >> 13;            // 0..1023

    // input: row stride 256 floats, plane stride 65536 floats
    const float4* row0 = (const float4*)(x + (size_t)nc * 65536u + (2u * oh) * 256u) + owp;
    const float4* row1 = row0 + 64;      // +256 floats = +64 float4

    float4 r0 = *row0;
    float4 r1 = *row1;

    float2 o;
    o.x = win_result(r0.x, r0.y, r1.x, r1.y);
    o.y = win_result(r0.z, r0.w, r1.z, r1.w);

    // output: plane stride 16384 floats, row stride 128 floats
    float2* dst = (float2*)(out + (size_t)nc * 16384u + oh * 128u) + owp;
    *dst = o;
}

extern "C" void kernel_launch(void* const* d_in, const int* in_sizes, int n_in,
                              void* d_out, int out_size) {
    const float* x = (const float*)d_in[0];
    float* out = (float*)d_out;
    // 8388608 threads total
    maxabspool_kernel<<<32768, 256>>>(x, out);
}

// round 2
// speedup vs baseline: 1.0106x; 1.0106x over previous
#include <cuda_runtime.h>

// x: [16, 64, 256, 256] f32  ->  out: [16, 64, 128, 128] f32
// Per 2x2 window: m = max|v_i|; out = max_i(|v_i|==m ? v_i : 0).
// NC = 1024, H=W=256, OH=OW=128.
// One thread -> 4 output pixels (8-wide input span):
//   4x LDG.128 (streaming) + 1x STG.128 (streaming).

static __device__ __forceinline__ float win_result(float a, float b, float c, float d) {
    float aa = fabsf(a), ab = fabsf(b), ac = fabsf(c), ad = fabsf(d);
    float m = fmaxf(fmaxf(aa, ab), fmaxf(ac, ad));
    float r = fmaxf(fmaxf(aa == m ? a : 0.0f, ab == m ? b : 0.0f),
                    fmaxf(ac == m ? c : 0.0f, ad == m ? d : 0.0f));
    return r;
}

__global__ __launch_bounds__(256) void maxabspool_kernel(
    const float* __restrict__ x, float* __restrict__ out)
{
    // total threads = NC * OH * (OW/4) = 1024 * 128 * 32 = 4194304
    unsigned idx = blockIdx.x * 256u + threadIdx.x;

    unsigned owq = idx & 31u;            // output quad index, 0..31 (4 px each)
    unsigned oh  = (idx >> 5) & 127u;    // 0..127
    unsigned nc  = idx >> 12;            // 0..1023

    // input: row stride 256 floats (=64 float4), plane stride 65536 floats
    const float4* base = (const float4*)(x + (size_t)nc * 65536u + (2u * oh) * 256u)
                         + 2u * owq;

    // front-batched loads: MLP=4, streaming (read-once)
    float4 a0 = __ldcs(base);            // row0, px 0..3
    float4 a1 = __ldcs(base + 1);        // row0, px 4..7
    float4 b0 = __ldcs(base + 64);       // row1, px 0..3
    float4 b1 = __ldcs(base + 65);       // row1, px 4..7

    float4 o;
    o.x = win_result(a0.x, a0.y, b0.x, b0.y);
    o.y = win_result(a0.z, a0.w, b0.z, b0.w);
    o.z = win_result(a1.x, a1.y, b1.x, b1.y);
    o.w = win_result(a1.z, a1.w, b1.z, b1.w);

    // output: plane stride 16384 floats, row stride 128 floats (=32 float4)
    float4* dst = (float4*)(out + (size_t)nc * 16384u + oh * 128u) + owq;
    __stcs(dst, o);
}

extern "C" void kernel_launch(void* const* d_in, const int* in_sizes, int n_in,
                              void* d_out, int out_size) {
    const float* x = (const float*)d_in[0];
    float* out = (float*)d_out;
    maxabspool_kernel<<<16384, 256>>>(x, out);
}